// round 5
// baseline (speedup 1.0000x reference)
#include <cuda_runtime.h>
#include <math.h>

// Problem geometry
#define C_    80
#define H_    128
#define W_    256
#define HW_   32768          // H_*W_
#define CHW_  2621440        // C_*HW_
#define D_    256
#define P_    131072         // 256*512 embedding spatial
#define KTOP  50
#define NBINS 2048
#define CAP   65536
#define SELN  4096
#define GEMM_BLOCKS 512      // 256 col-blocks x 2 row-halves
#define OUT_SCORES 6553600   // KTOP * P_
#define OUT_CATS   6553650

typedef unsigned long long u64;

// ---------------- scratch (static device globals; no allocation) -------------
__device__ float g_masked[CHW_];
__device__ int   g_hist[NBINS];      // zero-init at load; self-zeroed per replay
__device__ int   g_thresh_bin;
__device__ int   g_cand_cnt;         // reset by select_kernel each replay
__device__ float g_cand_val[CAP];
__device__ int   g_cand_idx[CAP];
__device__ float g_scores[KTOP];
__device__ int   g_spatial[KTOP];
__device__ int   g_cats[KTOP];
__device__ u64   g_A2[2 * D_ * 13];          // [half][d][13] k-pair-packed A
__device__ float g_psum[GEMM_BLOCKS * 25];
__device__ float g_pcnt[GEMM_BLOCKS * 25];

__device__ __forceinline__ float fast_sigmoid(float x) {
    return 1.0f / (1.0f + __expf(-x));
}

// packed f32x2 helpers (sm_100+)
__device__ __forceinline__ u64 pk2(float x, float y) {
    u64 r;
    asm("mov.b64 %0, {%1, %2};" : "=l"(r) : "f"(x), "f"(y));
    return r;
}
__device__ __forceinline__ u64 fma2(u64 a, u64 b, u64 c) {
    u64 d;
    asm("fma.rn.f32x2 %0, %1, %2, %3;" : "=l"(d) : "l"(a), "l"(b), "l"(c));
    return d;
}
__device__ __forceinline__ void upk2(u64 v, float& x, float& y) {
    asm("mov.b64 {%0, %1}, %2;" : "=f"(x), "=f"(y) : "l"(v));
}

// ---------------- 1: fused sigmoid + avg3 + max3 + peak mask + histogram -----
#define SW 260
__global__ void __launch_bounds__(256) fused_detect(const float* __restrict__ x) {
    __shared__ float s_sig[20 * SW];
    __shared__ float s_cent[18 * SW];
    __shared__ int   s_hist[NBINS];

    int c   = blockIdx.y;
    int r0  = blockIdx.x * 16;
    int tid = threadIdx.x;

    for (int i = tid; i < NBINS; i += 256) s_hist[i] = 0;

    const float* base = x + c * HW_;

    for (int i = tid; i < 20 * 256; i += 256) {
        int row = i >> 8;
        int col = i & 255;
        int gr  = r0 - 2 + row;
        float v = 0.0f;
        if (gr >= 0 && gr < H_) v = fast_sigmoid(base[gr * W_ + col]);
        s_sig[row * SW + col + 1] = v;
        if (col == 0)   s_sig[row * SW + 0]   = 0.0f;
        if (col == 255) s_sig[row * SW + 257] = 0.0f;
    }
    __syncthreads();

    for (int i = tid; i < 18 * 256; i += 256) {
        int rj  = i >> 8;
        int col = i & 255;
        int gr  = r0 - 1 + rj;
        float v = 0.0f;
        if (gr >= 0 && gr < H_) {
            float sum = 0.0f;
            #pragma unroll
            for (int dr = 0; dr < 3; dr++) {
                const float* p = s_sig + (rj + dr) * SW + col;
                sum += p[0] + p[1] + p[2];
            }
            float center = s_sig[(rj + 1) * SW + col + 1];
            v = 0.5f * (center + sum * (1.0f / 9.0f));
        }
        s_cent[rj * SW + col + 1] = v;
        if (col == 0)   s_cent[rj * SW + 0]   = 0.0f;
        if (col == 255) s_cent[rj * SW + 257] = 0.0f;
    }
    __syncthreads();

    for (int i = tid; i < 16 * 256; i += 256) {
        int ri  = i >> 8;
        int col = i & 255;
        float m = 0.0f;
        #pragma unroll
        for (int dr = 0; dr < 3; dr++) {
            const float* p = s_cent + (ri + dr) * SW + col;
            m = fmaxf(m, fmaxf(p[0], fmaxf(p[1], p[2])));
        }
        float cv = s_cent[(ri + 1) * SW + col + 1];
        float v  = (m == cv) ? cv : 0.0f;
        g_masked[c * HW_ + (r0 + ri) * W_ + col] = v;
        int bin = (int)(v * (float)NBINS);
        bin = bin < 0 ? 0 : (bin > NBINS - 1 ? NBINS - 1 : bin);
        atomicAdd(&s_hist[bin], 1);
    }
    __syncthreads();
    for (int i = tid; i < NBINS; i += 256)
        if (s_hist[i]) atomicAdd(&g_hist[i], s_hist[i]);
}

// ---------------- 2: threshold bin via suffix-sum; self-zero hist ------------
__global__ void thresh_kernel() {
    __shared__ int a[NBINS], b[NBINS];
    int t = threadIdx.x;   // 1024
    for (int i = t; i < NBINS; i += 1024) a[i] = g_hist[i];
    __syncthreads();
    int* src = a; int* dst = b;
    for (int off = 1; off < NBINS; off <<= 1) {
        for (int i = t; i < NBINS; i += 1024)
            dst[i] = src[i] + ((i + off < NBINS) ? src[i + off] : 0);
        __syncthreads();
        int* tmp = src; src = dst; dst = tmp;
    }
    for (int i = t; i < NBINS; i += 1024) {
        if (i >= 1 && src[i] >= KTOP && (i == NBINS - 1 || src[i + 1] < KTOP))
            g_thresh_bin = i;
    }
    if (t == 0 && src[1] < KTOP) g_thresh_bin = 1;
    for (int i = t; i < NBINS; i += 1024) g_hist[i] = 0;
}

// ---------------- 3: collect candidates --------------------------------------
__global__ void collect_kernel() {
    int i = blockIdx.x * blockDim.x + threadIdx.x;
    if (i >= CHW_) return;
    float v = g_masked[i];
    int tb = g_thresh_bin;
    if (tb < 1) tb = 1;
    int bin = (int)(v * (float)NBINS);
    bin = bin < 0 ? 0 : (bin > NBINS - 1 ? NBINS - 1 : bin);
    if (bin >= tb && v > 0.0f) {
        int pos = atomicAdd(&g_cand_cnt, 1);
        if (pos < CAP) { g_cand_val[pos] = v; g_cand_idx[pos] = i; }
    }
}

// ---------------- 4: top-50 via exact rank (distinct u64 keys) ---------------
__global__ void __launch_bounds__(1024) select_kernel() {
    __shared__ u64 keys[SELN];
    int t = threadIdx.x;
    int n = g_cand_cnt;
    if (n > SELN) n = SELN;

    if (t < KTOP) { g_scores[t] = 0.0f; g_cats[t] = 0; g_spatial[t] = 0; }

    for (int i = t; i < n; i += 1024) {
        unsigned int vb = __float_as_uint(g_cand_val[i]);
        unsigned int ix = ~(unsigned int)g_cand_idx[i];
        keys[i] = ((u64)vb << 32) | ix;
    }
    __syncthreads();

    for (int i = t; i < n; i += 1024) {
        u64 ki = keys[i];
        int rank = 0;
        for (int j = 0; j < n; j++) rank += (keys[j] > ki);
        if (rank < KTOP) {
            unsigned int vb  = (unsigned int)(ki >> 32);
            unsigned int idx = ~(unsigned int)(ki & 0xffffffffull);
            g_scores[rank]  = __uint_as_float(vb);
            g_cats[rank]    = (int)(idx >> 15);          // / HW_
            g_spatial[rank] = (int)(idx & (HW_ - 1));    // % HW_
        }
    }
    if (t == 0) g_cand_cnt = 0;   // reset for next replay
}

// ---------------- 5: gather A into [half][d][13] k-pair-packed u64 -----------
__global__ void gather_kernel(const float* __restrict__ ks) {
    int k    = blockIdx.x;
    int sp   = g_spatial[k];
    int half = k / 25;
    int lr   = k % 25;
    int p    = lr >> 1;
    int slot = lr & 1;
    float* A2f = (float*)g_A2;
    int d = threadIdx.x;   // 256 threads == D_
    float v = ks[d * HW_ + sp];
    int base = (half * D_ * 13 + d * 13 + p) * 2;
    A2f[base + slot] = v;
    if (lr == 24) A2f[base + 1] = 0.0f;   // pad slot of last (odd) pair
}

// ---------------- 6: GEMM [25,256]x[256,512cols/block] + sigmoid + rescore ---
// grid 512: colblk = bx>>1 (512 cols each), half = bx&1 (25 rows each).
// 4-deep LDG prefetch ring (MLP=4) hides the 577-cyc DRAM latency.
__global__ void __launch_bounds__(128, 3) gemm_kernel(const float* __restrict__ emb,
                                                      float* __restrict__ out) {
    __shared__ u64   As[D_ * 13];
    __shared__ float redS[4 * 25];
    __shared__ float redC[4 * 25];

    int tid    = threadIdx.x;
    int half   = blockIdx.x & 1;
    int colblk = blockIdx.x >> 1;

    const u64* src = g_A2 + half * D_ * 13;
    for (int i = tid; i < D_ * 13; i += 128) As[i] = src[i];
    __syncthreads();

    int c0 = colblk * 512 + tid * 4;
    const float4* ep = (const float4*)(emb + c0);    // stride P_/4 per d

    u64 acc[13][4];
    #pragma unroll
    for (int p = 0; p < 13; p++)
        #pragma unroll
        for (int c = 0; c < 4; c++) acc[p][c] = 0ull;

    // prefetch ring, depth 4
    float4 buf[4];
    #pragma unroll
    for (int j = 0; j < 4; j++) buf[j] = __ldg(&ep[j * (P_ / 4)]);

    for (int d0 = 0; d0 < D_; d0 += 4) {
        #pragma unroll
        for (int j = 0; j < 4; j++) {
            float4 cur = buf[j];
            int dn = d0 + 4 + j;
            if (dn < D_) buf[j] = __ldg(&ep[dn * (P_ / 4)]);
            u64 e0 = pk2(cur.x, cur.x);
            u64 e1 = pk2(cur.y, cur.y);
            u64 e2 = pk2(cur.z, cur.z);
            u64 e3 = pk2(cur.w, cur.w);
            const u64* a = As + (d0 + j) * 13;
            #pragma unroll
            for (int p = 0; p < 13; p++) {
                u64 av = a[p];
                acc[p][0] = fma2(av, e0, acc[p][0]);
                acc[p][1] = fma2(av, e1, acc[p][1]);
                acc[p][2] = fma2(av, e2, acc[p][2]);
                acc[p][3] = fma2(av, e3, acc[p][3]);
            }
        }
    }

    // epilogue: rows 0..24 (global row = half*25 + lr), lr = 2p+slot
    int lane = tid & 31, warp = tid >> 5;
    int rbase = half * 25;
    #pragma unroll
    for (int p = 0; p < 13; p++) {
        float lo[4], hi[4];
        #pragma unroll
        for (int c = 0; c < 4; c++) upk2(acc[p][c], lo[c], hi[c]);

        // row lr = 2p (always valid)
        {
            float4 st;
            float m0 = fast_sigmoid(lo[0]), m1 = fast_sigmoid(lo[1]);
            float m2 = fast_sigmoid(lo[2]), m3 = fast_sigmoid(lo[3]);
            st.x = m0; st.y = m1; st.z = m2; st.w = m3;
            *(float4*)(out + (rbase + 2 * p) * P_ + c0) = st;
            float s  = (m0 > 0.4f ? m0 : 0.0f) + (m1 > 0.4f ? m1 : 0.0f)
                     + (m2 > 0.4f ? m2 : 0.0f) + (m3 > 0.4f ? m3 : 0.0f);
            float cn = (m0 > 0.4f ? 1.0f : 0.0f) + (m1 > 0.4f ? 1.0f : 0.0f)
                     + (m2 > 0.4f ? 1.0f : 0.0f) + (m3 > 0.4f ? 1.0f : 0.0f);
            #pragma unroll
            for (int o = 16; o > 0; o >>= 1) {
                s  += __shfl_down_sync(0xffffffffu, s,  o);
                cn += __shfl_down_sync(0xffffffffu, cn, o);
            }
            if (lane == 0) { redS[warp * 25 + 2 * p] = s; redC[warp * 25 + 2 * p] = cn; }
        }
        // row lr = 2p+1 (skip pad at p == 12)
        if (p < 12) {
            float4 st;
            float m0 = fast_sigmoid(hi[0]), m1 = fast_sigmoid(hi[1]);
            float m2 = fast_sigmoid(hi[2]), m3 = fast_sigmoid(hi[3]);
            st.x = m0; st.y = m1; st.z = m2; st.w = m3;
            *(float4*)(out + (rbase + 2 * p + 1) * P_ + c0) = st;
            float s  = (m0 > 0.4f ? m0 : 0.0f) + (m1 > 0.4f ? m1 : 0.0f)
                     + (m2 > 0.4f ? m2 : 0.0f) + (m3 > 0.4f ? m3 : 0.0f);
            float cn = (m0 > 0.4f ? 1.0f : 0.0f) + (m1 > 0.4f ? 1.0f : 0.0f)
                     + (m2 > 0.4f ? 1.0f : 0.0f) + (m3 > 0.4f ? 1.0f : 0.0f);
            #pragma unroll
            for (int o = 16; o > 0; o >>= 1) {
                s  += __shfl_down_sync(0xffffffffu, s,  o);
                cn += __shfl_down_sync(0xffffffffu, cn, o);
            }
            if (lane == 0) { redS[warp * 25 + 2 * p + 1] = s; redC[warp * 25 + 2 * p + 1] = cn; }
        }
    }
    __syncthreads();
    if (tid < 25) {
        float s  = redS[tid] + redS[25 + tid] + redS[50 + tid] + redS[75 + tid];
        float cn = redC[tid] + redC[25 + tid] + redC[50 + tid] + redC[75 + tid];
        g_psum[blockIdx.x * 25 + tid] = s;
        g_pcnt[blockIdx.x * 25 + tid] = cn;
    }
}

// ---------------- 7: final scores/cats ---------------------------------------
__global__ void final_kernel(float* __restrict__ out) {
    int k = threadIdx.x;
    if (k >= KTOP) return;
    int half = k / 25;
    int lr   = k % 25;
    float s = 0.0f, cn = 0.0f;
    for (int cb = 0; cb < 256; cb++) {
        int b = cb * 2 + half;
        s  += g_psum[b * 25 + lr];
        cn += g_pcnt[b * 25 + lr];
    }
    float factor = s / fmaxf(cn, 1e-8f);
    float sc = g_scores[k];
    float valid = (sc > 0.1f) ? 1.0f : 0.0f;
    out[OUT_SCORES + k] = sc * factor * valid;
    out[OUT_CATS + k]   = (float)g_cats[k];
}

// ---------------- launch -----------------------------------------------------
extern "C" void kernel_launch(void* const* d_in, const int* in_sizes, int n_in,
                              void* d_out, int out_size) {
    const float* thing_map    = (const float*)d_in[0];
    const float* kernel_space = (const float*)d_in[1];
    const float* embeddings   = (const float*)d_in[2];
    float* out = (float*)d_out;

    fused_detect<<<dim3(8, 80), 256>>>(thing_map);             // 1
    thresh_kernel<<<1, 1024>>>();                              // 2
    collect_kernel<<<(CHW_ + 255) / 256, 256>>>();             // 3
    select_kernel<<<1, 1024>>>();                              // 4
    gather_kernel<<<KTOP, 256>>>(kernel_space);                // 5
    gemm_kernel<<<GEMM_BLOCKS, 128>>>(embeddings, out);        // 6
    final_kernel<<<1, 64>>>(out);                              // 7
}

// round 7
// speedup vs baseline: 1.1711x; 1.1711x over previous
#include <cuda_runtime.h>
#include <cuda_bf16.h>
#include <math.h>
#include <stdint.h>

// Problem geometry
#define C_    80
#define H_    128
#define W_    256
#define HW_   32768
#define CHW_  2621440
#define D_    256
#define P_    131072
#define KTOP  50
#define NBINS 2048
#define CAP   65536
#define SELN  4096
#define GEMM_BLOCKS 512      // each CTA: 2 p-tiles of 128 cols
#define OUT_SCORES 6553600
#define OUT_CATS   6553650

#define KSM_PAD   72         // u32 words per dp-row (64 + 8 bank pad)
#define TROW      136        // bf16 per A-tile row (128 + 8) = 272B
#define TILE_HALF 4352       // 16*136*2 bytes (one split)
#define TILE_BUF  8704       // hi+lo
#define OFF_KSM_LO 36864
#define OFF_TILES  73728
#define SMEM_DYN  107520     // 73728 + 64*132*4

typedef unsigned long long u64;

// ---------------- scratch ----------------------------------------------------
__device__ float g_masked[CHW_];
__device__ int   g_hist[NBINS];
__device__ int   g_thresh_bin;
__device__ int   g_blocks_done;
__device__ int   g_cand_cnt;
__device__ float g_cand_val[CAP];
__device__ int   g_cand_idx[CAP];
__device__ float g_scores[KTOP];
__device__ int   g_spatial[KTOP];
__device__ int   g_cats[KTOP];
__device__ uint32_t g_Ahi2[128 * 64];   // [dp][n] bf16x2 (d-pair packed) hi
__device__ uint32_t g_Alo2[128 * 64];   // lo
__device__ float g_psum[GEMM_BLOCKS * KTOP];
__device__ float g_pcnt[GEMM_BLOCKS * KTOP];

__device__ __forceinline__ float fast_sigmoid(float x) {
    return 1.0f / (1.0f + __expf(-x));
}
__device__ __forceinline__ uint32_t smem_u32(const void* p) {
    uint32_t a;
    asm("{ .reg .u64 t; cvta.to.shared.u64 t, %1; cvt.u32.u64 %0, t; }"
        : "=r"(a) : "l"(p));
    return a;
}
__device__ __forceinline__ uint32_t pack_bf16x2(__nv_bfloat16 e0, __nv_bfloat16 e1) {
    return (uint32_t)__bfloat16_as_ushort(e0) |
           ((uint32_t)__bfloat16_as_ushort(e1) << 16);
}
__device__ __forceinline__ void mma_bf16(float c[4], uint32_t a0, uint32_t a1,
                                         uint32_t a2, uint32_t a3,
                                         uint32_t b0, uint32_t b1) {
    asm volatile(
        "mma.sync.aligned.m16n8k16.row.col.f32.bf16.bf16.f32 "
        "{%0,%1,%2,%3}, {%4,%5,%6,%7}, {%8,%9}, {%0,%1,%2,%3};"
        : "+f"(c[0]), "+f"(c[1]), "+f"(c[2]), "+f"(c[3])
        : "r"(a0), "r"(a1), "r"(a2), "r"(a3), "r"(b0), "r"(b1));
}
__device__ __forceinline__ void ldm_x4_trans(uint32_t& r0, uint32_t& r1,
                                             uint32_t& r2, uint32_t& r3,
                                             uint32_t addr) {
    asm volatile(
        "ldmatrix.sync.aligned.m8n8.x4.trans.shared.b16 {%0,%1,%2,%3}, [%4];"
        : "=r"(r0), "=r"(r1), "=r"(r2), "=r"(r3) : "r"(addr));
}

// ---------------- 1: fused detect + (last block) threshold -------------------
#define SW 260
__global__ void __launch_bounds__(256) fused_detect(const float* __restrict__ x) {
    __shared__ float s_sig[20 * SW];
    __shared__ float s_cent[18 * SW];
    __shared__ int   s_hist[NBINS];
    __shared__ int   s_last;

    int c   = blockIdx.y;
    int r0  = blockIdx.x * 16;
    int tid = threadIdx.x;

    for (int i = tid; i < NBINS; i += 256) s_hist[i] = 0;

    const float* base = x + c * HW_;

    for (int i = tid; i < 20 * 256; i += 256) {
        int row = i >> 8;
        int col = i & 255;
        int gr  = r0 - 2 + row;
        float v = 0.0f;
        if (gr >= 0 && gr < H_) v = fast_sigmoid(base[gr * W_ + col]);
        s_sig[row * SW + col + 1] = v;
        if (col == 0)   s_sig[row * SW + 0]   = 0.0f;
        if (col == 255) s_sig[row * SW + 257] = 0.0f;
    }
    __syncthreads();

    for (int i = tid; i < 18 * 256; i += 256) {
        int rj  = i >> 8;
        int col = i & 255;
        int gr  = r0 - 1 + rj;
        float v = 0.0f;
        if (gr >= 0 && gr < H_) {
            float sum = 0.0f;
            #pragma unroll
            for (int dr = 0; dr < 3; dr++) {
                const float* p = s_sig + (rj + dr) * SW + col;
                sum += p[0] + p[1] + p[2];
            }
            float center = s_sig[(rj + 1) * SW + col + 1];
            v = 0.5f * (center + sum * (1.0f / 9.0f));
        }
        s_cent[rj * SW + col + 1] = v;
        if (col == 0)   s_cent[rj * SW + 0]   = 0.0f;
        if (col == 255) s_cent[rj * SW + 257] = 0.0f;
    }
    __syncthreads();

    for (int i = tid; i < 16 * 256; i += 256) {
        int ri  = i >> 8;
        int col = i & 255;
        float m = 0.0f;
        #pragma unroll
        for (int dr = 0; dr < 3; dr++) {
            const float* p = s_cent + (ri + dr) * SW + col;
            m = fmaxf(m, fmaxf(p[0], fmaxf(p[1], p[2])));
        }
        float cv = s_cent[(ri + 1) * SW + col + 1];
        float v  = (m == cv) ? cv : 0.0f;
        g_masked[c * HW_ + (r0 + ri) * W_ + col] = v;
        int bin = (int)(v * (float)NBINS);
        bin = bin < 0 ? 0 : (bin > NBINS - 1 ? NBINS - 1 : bin);
        atomicAdd(&s_hist[bin], 1);
    }
    __syncthreads();
    for (int i = tid; i < NBINS; i += 256)
        if (s_hist[i]) atomicAdd(&g_hist[i], s_hist[i]);

    __threadfence();
    __syncthreads();
    if (tid == 0) {
        int done = atomicAdd(&g_blocks_done, 1);
        s_last = (done == gridDim.x * gridDim.y - 1) ? 1 : 0;
    }
    __syncthreads();
    if (!s_last) return;
    __threadfence();

    int* sa = s_hist;
    int* sb = (int*)s_sig;
    for (int i = tid; i < NBINS; i += 256) sa[i] = g_hist[i];
    __syncthreads();
    int* src = sa; int* dst = sb;
    for (int off = 1; off < NBINS; off <<= 1) {
        for (int i = tid; i < NBINS; i += 256)
            dst[i] = src[i] + ((i + off < NBINS) ? src[i + off] : 0);
        __syncthreads();
        int* t2 = src; src = dst; dst = t2;
    }
    for (int i = tid; i < NBINS; i += 256) {
        if (i >= 1 && src[i] >= KTOP && (i == NBINS - 1 || src[i + 1] < KTOP))
            g_thresh_bin = i;
    }
    if (tid == 0 && src[1] < KTOP) g_thresh_bin = 1;
    for (int i = tid; i < NBINS; i += 256) g_hist[i] = 0;
    if (tid == 0) g_blocks_done = 0;
}

// ---------------- 2: collect candidates --------------------------------------
__global__ void collect_kernel() {
    int i = blockIdx.x * blockDim.x + threadIdx.x;
    if (i >= CHW_) return;
    float v = g_masked[i];
    int tb = g_thresh_bin;
    if (tb < 1) tb = 1;
    int bin = (int)(v * (float)NBINS);
    bin = bin < 0 ? 0 : (bin > NBINS - 1 ? NBINS - 1 : bin);
    if (bin >= tb && v > 0.0f) {
        int pos = atomicAdd(&g_cand_cnt, 1);
        if (pos < CAP) { g_cand_val[pos] = v; g_cand_idx[pos] = i; }
    }
}

// ---------------- 3: top-50 via exact rank + A gather/split ------------------
__global__ void __launch_bounds__(1024) select_kernel(const float* __restrict__ ks) {
    __shared__ u64 keys[SELN];
    int t = threadIdx.x;
    int n = g_cand_cnt;
    if (n > SELN) n = SELN;

    if (t < KTOP) { g_scores[t] = 0.0f; g_cats[t] = 0; g_spatial[t] = 0; }

    for (int i = t; i < n; i += 1024) {
        unsigned int vb = __float_as_uint(g_cand_val[i]);
        unsigned int ix = ~(unsigned int)g_cand_idx[i];
        keys[i] = ((u64)vb << 32) | ix;
    }
    __syncthreads();

    for (int i = t; i < n; i += 1024) {
        u64 ki = keys[i];
        int rank = 0;
        for (int j = 0; j < n; j++) rank += (keys[j] > ki);
        if (rank < KTOP) {
            unsigned int vb  = (unsigned int)(ki >> 32);
            unsigned int idx = ~(unsigned int)(ki & 0xffffffffull);
            g_scores[rank]  = __uint_as_float(vb);
            g_cats[rank]    = (int)(idx >> 15);
            g_spatial[rank] = (int)(idx & (HW_ - 1));
        }
    }
    if (t == 0) g_cand_cnt = 0;
    __syncthreads();

    // A prep: [dp][n] bf16x2 hi/lo, n in 0..63 (zeros for n >= 50)
    for (int i = t; i < 128 * 64; i += 1024) {
        int dp = i >> 6;
        int nn = i & 63;
        uint32_t hp = 0u, lp = 0u;
        if (nn < KTOP) {
            int sp = g_spatial[nn];
            float v0 = ks[(2 * dp) * HW_ + sp];
            float v1 = ks[(2 * dp + 1) * HW_ + sp];
            __nv_bfloat16 h0 = __float2bfloat16(v0);
            __nv_bfloat16 h1 = __float2bfloat16(v1);
            __nv_bfloat16 l0 = __float2bfloat16(v0 - __bfloat162float(h0));
            __nv_bfloat16 l1 = __float2bfloat16(v1 - __bfloat162float(h1));
            hp = pack_bf16x2(h0, h1);
            lp = pack_bf16x2(l0, l1);
        }
        g_Ahi2[i] = hp;
        g_Alo2[i] = lp;
    }
}

// ---------------- 4: mma.sync bf16 GEMM + sigmoid + rescore ------------------
// 512 CTAs x 256 threads; each CTA: 2 p-tiles of 128 cols, M(p)=128, N(kern)=64,
// K(d)=256 in 16 chunks. A = emb (hi/lo bf16 smem tiles + ldmatrix.trans),
// B = kernels (prepacked bf16x2 in smem). C += Ahi*Bhi + Ahi*Blo + Alo*Bhi.
__global__ void __launch_bounds__(256) gemm_kernel(const float* __restrict__ emb,
                                                   float* __restrict__ out) {
    extern __shared__ __align__(16) char dsm[];
    __shared__ float redS[8 * KTOP];
    __shared__ float redC[8 * KTOP];

    uint32_t* ksmHi = (uint32_t*)dsm;                       // [128][72]
    uint32_t* ksmLo = (uint32_t*)(dsm + OFF_KSM_LO);
    char*     tiles = dsm + OFF_TILES;                      // 2 bufs of hi+lo
    float*    cout  = (float*)(dsm + OFF_TILES);            // union after mma

    int tid  = threadIdx.x;
    int wid  = tid >> 5;
    int lane = tid & 31;
    int tig  = lane & 3;
    int gp   = lane >> 2;

    // stage kernels into smem (bank-padded rows)
    for (int i = tid; i < 128 * 64; i += 256) {
        int dp = i >> 6, nn = i & 63;
        ksmHi[dp * KSM_PAD + nn] = g_Ahi2[i];
        ksmLo[dp * KSM_PAD + nn] = g_Alo2[i];
    }

    for (int i = tid; i < 8 * KTOP; i += 256) { redS[i] = 0.0f; redC[i] = 0.0f; }

    // ldmatrix address components (within a 16-row tile)
    int lgrp = lane >> 3;                       // matrix index 0..3
    int lrow = ((lgrp & 2) ? 8 : 0) + (lane & 7);
    int lcol = wid * 16 + ((lgrp & 1) ? 8 : 0);
    uint32_t tiles_u32 = smem_u32(tiles);
    uint32_t ldm_off = (uint32_t)(lrow * (TROW * 2) + lcol * 2);

    int pcol = tid & 127;     // staging column
    int half = tid >> 7;      // staging row half

    for (int tile = 0; tile < 2; tile++) {
        int p0 = blockIdx.x * 256 + tile * 128;

        float c[8][4];
        #pragma unroll
        for (int nt = 0; nt < 8; nt++)
            #pragma unroll
            for (int j = 0; j < 4; j++) c[nt][j] = 0.0f;

        // prefetch chunk 0
        float pf[8];
        {
            const float* e0 = emb + (size_t)(half * 8) * P_ + p0 + pcol;
            #pragma unroll
            for (int j = 0; j < 8; j++) pf[j] = __ldg(e0 + (size_t)j * P_);
        }

        for (int ck = 0; ck < 16; ck++) {
            // stage pf -> bf16 hi/lo tiles (buffer ck&1)
            char* thb = tiles + (ck & 1) * TILE_BUF;
            char* tlb = thb + TILE_HALF;
            #pragma unroll
            for (int j = 0; j < 8; j++) {
                int row = half * 8 + j;
                float v = pf[j];
                __nv_bfloat16 hv = __float2bfloat16(v);
                __nv_bfloat16 lv = __float2bfloat16(v - __bfloat162float(hv));
                *(uint16_t*)(thb + row * (TROW * 2) + pcol * 2) = __bfloat16_as_ushort(hv);
                *(uint16_t*)(tlb + row * (TROW * 2) + pcol * 2) = __bfloat16_as_ushort(lv);
            }
            // prefetch next chunk (overlaps mma below)
            if (ck < 15) {
                const float* e0 = emb + (size_t)((ck + 1) * 16 + half * 8) * P_ + p0 + pcol;
                #pragma unroll
                for (int j = 0; j < 8; j++) pf[j] = __ldg(e0 + (size_t)j * P_);
            }
            __syncthreads();

            // A frags
            uint32_t ah0, ah1, ah2, ah3, al0, al1, al2, al3;
            uint32_t hb = tiles_u32 + (uint32_t)((ck & 1) * TILE_BUF) + ldm_off;
            ldm_x4_trans(ah0, ah1, ah2, ah3, hb);
            ldm_x4_trans(al0, al1, al2, al3, hb + TILE_HALF);

            // B frags + mma per n-tile
            int dpb = ck * 8;
            #pragma unroll
            for (int nt = 0; nt < 8; nt++) {
                int nb = nt * 8 + gp;
                uint32_t bh0 = ksmHi[(dpb + tig) * KSM_PAD + nb];
                uint32_t bh1 = ksmHi[(dpb + 4 + tig) * KSM_PAD + nb];
                uint32_t bl0 = ksmLo[(dpb + tig) * KSM_PAD + nb];
                uint32_t bl1 = ksmLo[(dpb + 4 + tig) * KSM_PAD + nb];
                mma_bf16(c[nt], ah0, ah1, ah2, ah3, bh0, bh1);
                mma_bf16(c[nt], ah0, ah1, ah2, ah3, bl0, bl1);
                mma_bf16(c[nt], al0, al1, al2, al3, bh0, bh1);
            }
        }

        // epilogue: C frags -> cout [64 n][132 p]
        __syncthreads();          // all ldmatrix reads of tiles done
        int prow = wid * 16 + gp; // local p for c0/c1 rows; +8 for c2/c3
        #pragma unroll
        for (int nt = 0; nt < 8; nt++) {
            int nc = nt * 8 + 2 * tig;
            cout[nc * 132 + prow]           = c[nt][0];
            cout[(nc + 1) * 132 + prow]     = c[nt][1];
            cout[nc * 132 + prow + 8]       = c[nt][2];
            cout[(nc + 1) * 132 + prow + 8] = c[nt][3];
        }
        __syncthreads();

        // sigmoid + coalesced store + rescore (2 rows per pass)
        for (int rr = 0; rr < 25; rr++) {
            int r = 2 * rr + half;
            float v = cout[r * 132 + pcol];
            float m = fast_sigmoid(v);
            out[(size_t)r * P_ + p0 + pcol] = m;
            float sv = m > 0.4f ? m : 0.0f;
            float cv = m > 0.4f ? 1.0f : 0.0f;
            #pragma unroll
            for (int o = 16; o > 0; o >>= 1) {
                sv += __shfl_down_sync(0xffffffffu, sv, o);
                cv += __shfl_down_sync(0xffffffffu, cv, o);
            }
            if (lane == 0) { redS[wid * KTOP + r] += sv; redC[wid * KTOP + r] += cv; }
        }
        __syncthreads();          // cout/tiles reusable next tile
    }

    if (tid < KTOP) {
        float s = 0.0f, cn = 0.0f;
        #pragma unroll
        for (int w = 0; w < 8; w++) { s += redS[w * KTOP + tid]; cn += redC[w * KTOP + tid]; }
        g_psum[blockIdx.x * KTOP + tid] = s;
        g_pcnt[blockIdx.x * KTOP + tid] = cn;
    }
}

// ---------------- 5: final scores/cats ---------------------------------------
__global__ void __launch_bounds__(512) final_kernel(float* __restrict__ out) {
    __shared__ float fs[400], fc[400];
    int tid = threadIdx.x;
    if (tid < 400) {
        int k = tid >> 3, slice = tid & 7;
        float s = 0.0f, cn = 0.0f;
        for (int b = slice; b < GEMM_BLOCKS; b += 8) {
            s  += g_psum[b * KTOP + k];
            cn += g_pcnt[b * KTOP + k];
        }
        fs[tid] = s; fc[tid] = cn;
    }
    __syncthreads();
    if (tid < KTOP) {
        float s = 0.0f, cn = 0.0f;
        #pragma unroll
        for (int j = 0; j < 8; j++) { s += fs[tid * 8 + j]; cn += fc[tid * 8 + j]; }
        float factor = s / fmaxf(cn, 1e-8f);
        float sc = g_scores[tid];
        float valid = (sc > 0.1f) ? 1.0f : 0.0f;
        out[OUT_SCORES + tid] = sc * factor * valid;
        out[OUT_CATS + tid]   = (float)g_cats[tid];
    }
}

// ---------------- launch -----------------------------------------------------
extern "C" void kernel_launch(void* const* d_in, const int* in_sizes, int n_in,
                              void* d_out, int out_size) {
    const float* thing_map    = (const float*)d_in[0];
    const float* kernel_space = (const float*)d_in[1];
    const float* embeddings   = (const float*)d_in[2];
    float* out = (float*)d_out;

    cudaFuncSetAttribute(gemm_kernel,
                         cudaFuncAttributeMaxDynamicSharedMemorySize, SMEM_DYN);

    fused_detect<<<dim3(8, 80), 256>>>(thing_map);                 // 1
    collect_kernel<<<(CHW_ + 255) / 256, 256>>>();                 // 2
    select_kernel<<<1, 1024>>>(kernel_space);                      // 3
    gemm_kernel<<<GEMM_BLOCKS, 256, SMEM_DYN>>>(embeddings, out);  // 4 (profiled)
    final_kernel<<<1, 512>>>(out);                                 // 5
}